// round 1
// baseline (speedup 1.0000x reference)
#include <cuda_runtime.h>

#define IN_C   256
#define OUT_C  256
#define HW     32
#define NB     64
#define NPIX   (HW * HW)

// normalized int32 copies of y and sample_arc (input may be int32 or int64)
__device__ int g_y[NB];
__device__ int g_arc[NB];

// Detect whether the index buffers are int64 (little-endian, small non-negative
// values => every odd 32-bit word is zero) or int32, then normalize to int32.
__global__ void decode_idx(const int* __restrict__ yr, const int* __restrict__ ar) {
    __shared__ int is64;
    int t = threadIdx.x;
    if (t == 0) {
        int acc = 0;
        // first 64 words are safe to read in both layouts
        for (int i = 1; i < NB; i += 2) acc |= yr[i];
        is64 = (acc == 0) ? 1 : 0;
    }
    __syncthreads();
    if (t < NB) {
        int stride = is64 ? 2 : 1;
        g_y[t]   = yr[t * stride];
        g_arc[t] = ar[t * stride];
    }
}

// Direct conv, one template instantiation per kernel size.
// Block: 128 threads. Tile: 8 output channels x full 32x32 image per block row.
// Each thread: 8 pixels (tid, tid+128, ..., tid+896) x 8 ocs = 64 accumulators.
// Inner loop per (ic, r, s): 8 w-LDS + 8 x-LDS feed 64 FMA (4:1 FMA:LDS).
template<int K>
__global__ void __launch_bounds__(128, 4) conv_branch(
    const float* __restrict__ x, const float* __restrict__ w,
    const float* __restrict__ e, float* __restrict__ out, int branch)
{
    constexpr int PAD = K / 2;
    constexpr int PH  = HW + 2 * PAD;   // padded tile dim
    constexpr int ICB = 4;              // input channels per smem stage
    constexpr int OCT = 8;              // output channels per block

    const int b = blockIdx.y;
    if (g_arc[b] != branch) return;
    const int oc0 = blockIdx.x * OCT;

    __shared__ float xs[ICB][PH][PH];
    __shared__ float ws[ICB][OCT][K * K];

    const int tid  = threadIdx.x;
    const int col  = tid & 31;     // pixel column (same for all 8 pixels)
    const int row0 = tid >> 5;     // base pixel row; rows are row0 + 4*p

    float acc[8][OCT];
    #pragma unroll
    for (int p = 0; p < 8; p++)
        #pragma unroll
        for (int o = 0; o < OCT; o++)
            acc[p][o] = 0.0f;

    const float* xb = x + (b * IN_C) * NPIX;

    #pragma unroll 1
    for (int ic0 = 0; ic0 < IN_C; ic0 += ICB) {
        __syncthreads();
        // ---- stage x tiles (zero-filled halo) ----
        #pragma unroll 4
        for (int idx = tid; idx < ICB * PH * PH; idx += 128) {
            int ic  = idx / (PH * PH);
            int rem = idx - ic * (PH * PH);
            int ph  = rem / PH;
            int pw  = rem - ph * PH;
            int h  = ph - PAD;
            int wc = pw - PAD;
            float v = 0.0f;
            if ((unsigned)h < HW && (unsigned)wc < HW)
                v = xb[(ic0 + ic) * NPIX + h * HW + wc];
            xs[ic][ph][pw] = v;
        }
        // ---- stage weights ----
        #pragma unroll 4
        for (int idx = tid; idx < ICB * OCT * K * K; idx += 128) {
            int ic  = idx / (OCT * K * K);
            int rem = idx - ic * (OCT * K * K);
            int o   = rem / (K * K);
            int rs  = rem - o * (K * K);
            ws[ic][o][rs] = w[((oc0 + o) * IN_C + ic0 + ic) * (K * K) + rs];
        }
        __syncthreads();

        // ---- compute ----
        #pragma unroll 1
        for (int ic = 0; ic < ICB; ic++) {
            #pragma unroll 1
            for (int r = 0; r < K; r++) {
                #pragma unroll
                for (int s = 0; s < K; s++) {
                    float wv[OCT];
                    #pragma unroll
                    for (int o = 0; o < OCT; o++)
                        wv[o] = ws[ic][o][r * K + s];
                    #pragma unroll
                    for (int p = 0; p < 8; p++) {
                        float xv = xs[ic][row0 + 4 * p + r][col + s];
                        #pragma unroll
                        for (int o = 0; o < OCT; o++)
                            acc[p][o] = fmaf(xv, wv[o], acc[p][o]);
                    }
                }
            }
        }
    }

    // ---- epilogue: add class embedding, store ----
    const int yb = g_y[b];
    float ev[OCT];
    #pragma unroll
    for (int o = 0; o < OCT; o++)
        ev[o] = e[yb * OUT_C + oc0 + o];

    float* ob = out + (b * OUT_C + oc0) * NPIX;
    #pragma unroll
    for (int p = 0; p < 8; p++) {
        int pix = tid + 128 * p;   // == (row0 + 4*p) * 32 + col
        #pragma unroll
        for (int o = 0; o < OCT; o++)
            ob[o * NPIX + pix] = acc[p][o] + ev[o];
    }
}

extern "C" void kernel_launch(void* const* d_in, const int* in_sizes, int n_in,
                              void* d_out, int out_size) {
    const float* x = nullptr;
    const int*   yr = nullptr;
    const int*   ar = nullptr;
    const float* w[4] = {nullptr, nullptr, nullptr, nullptr};
    const float* e[4] = {nullptr, nullptr, nullptr, nullptr};
    int ne = 0, n64 = 0;

    for (int i = 0; i < n_in; i++) {
        int sz = in_sizes[i];
        const void* p = d_in[i];
        if      (sz == 16777216) x = (const float*)p;                        // [64,256,32,32]
        else if (sz == 64)       { if (n64++ == 0) yr = (const int*)p; else ar = (const int*)p; }
        else if (sz == 65536)    w[0] = (const float*)p;                     // k=1
        else if (sz == 589824)   w[1] = (const float*)p;                     // k=3
        else if (sz == 1638400)  w[2] = (const float*)p;                     // k=5
        else if (sz == 3211264)  w[3] = (const float*)p;                     // k=7
        else if (sz == 256000)   { if (ne < 4) e[ne++] = (const float*)p; }  // e0..e3 in order
    }

    decode_idx<<<1, 64>>>(yr, ar);

    float* out = (float*)d_out;
    dim3 grid(OUT_C / 8, NB);
    conv_branch<1><<<grid, 128>>>(x, w[0], e[0], out, 0);
    conv_branch<3><<<grid, 128>>>(x, w[1], e[1], out, 1);
    conv_branch<5><<<grid, 128>>>(x, w[2], e[2], out, 2);
    conv_branch<7><<<grid, 128>>>(x, w[3], e[3], out, 3);
}

// round 2
// speedup vs baseline: 1.0646x; 1.0646x over previous
#include <cuda_runtime.h>

#define IN_C   256
#define OUT_C  256
#define HW     32
#define NB     64
#define NPIX   (HW * HW)

__device__ int g_y[NB];
__device__ int g_arc[NB];

// Normalize y / sample_arc (int32 or int64) to int32.
__global__ void decode_idx(const int* __restrict__ yr, const int* __restrict__ ar) {
    __shared__ int is64;
    int t = threadIdx.x;
    if (t == 0) {
        int acc = 0;
        for (int i = 1; i < NB; i += 2) acc |= yr[i];
        is64 = (acc == 0) ? 1 : 0;
    }
    __syncthreads();
    if (t < NB) {
        int stride = is64 ? 2 : 1;
        g_y[t]   = yr[t * stride];
        g_arc[t] = ar[t * stride];
    }
}

// Direct conv, register-window formulation.
// Block: 128 threads, 8 output channels, full 32x32 image.
// Thread: row = tid>>2, 8 contiguous pixels starting at colseg=(tid&3)*8.
// Per (ic, r): load x window of 8+K-1 values once; per s: 2 LDS.128 of
// 8 weights (broadcast), 64 FMAs from registers.
template<int K>
__global__ void __launch_bounds__(128, 4) conv_branch(
    const float* __restrict__ x, const float* __restrict__ w,
    const float* __restrict__ e, float* __restrict__ out, int branch)
{
    constexpr int PAD = K / 2;
    constexpr int PH  = HW + 2 * PAD;           // padded tile dim
    constexpr int RS  = (PH % 2 == 0) ? PH + 1 : PH;  // odd row stride (bank skew)
    constexpr int ICB = 4;                      // input channels per stage
    constexpr int OCT = 8;                      // output channels per block
    constexpr int WIN = 8 + K - 1;              // register window width

    const int b = blockIdx.y;
    if (g_arc[b] != branch) return;
    const int oc0 = blockIdx.x * OCT;

    __shared__ float xs[ICB * PH * RS];
    __shared__ float ws[ICB * K * K * OCT];

    const int tid    = threadIdx.x;
    const int row    = tid >> 2;        // 0..31
    const int colseg = (tid & 3) * 8;   // 0,8,16,24

    float acc[OCT][8];
    #pragma unroll
    for (int o = 0; o < OCT; o++)
        #pragma unroll
        for (int j = 0; j < 8; j++)
            acc[o][j] = 0.0f;

    const float* xb = x + (b * IN_C) * NPIX;

    #pragma unroll 1
    for (int ic0 = 0; ic0 < IN_C; ic0 += ICB) {
        __syncthreads();
        // ---- stage x tiles (zero halo) ----
        #pragma unroll 4
        for (int idx = tid; idx < ICB * PH * PH; idx += 128) {
            int ic  = idx / (PH * PH);
            int rem = idx - ic * (PH * PH);
            int ph  = rem / PH;
            int pw  = rem - ph * PH;
            int h  = ph - PAD;
            int wc = pw - PAD;
            float v = 0.0f;
            if ((unsigned)h < HW && (unsigned)wc < HW)
                v = xb[(ic0 + ic) * NPIX + h * HW + wc];
            xs[ic * (PH * RS) + ph * RS + pw] = v;
        }
        // ---- stage weights, layout [ic][rs][oc] ----
        #pragma unroll 4
        for (int idx = tid; idx < ICB * K * K * OCT; idx += 128) {
            int ic  = idx / (K * K * OCT);
            int rem = idx - ic * (K * K * OCT);
            int rs  = rem / OCT;
            int o   = rem - rs * OCT;
            ws[idx] = w[((oc0 + o) * IN_C + ic0 + ic) * (K * K) + rs];
        }
        __syncthreads();

        // ---- compute ----
        #pragma unroll 1
        for (int ic = 0; ic < ICB; ic++) {
            const float* xrow0 = xs + ic * (PH * RS) + row * RS + colseg;
            const float* wrow  = ws + ic * (K * K * OCT);
            #pragma unroll 1
            for (int r = 0; r < K; r++) {
                float xwin[WIN];
                const float* xr = xrow0 + r * RS;
                #pragma unroll
                for (int j = 0; j < WIN; j++)
                    xwin[j] = xr[j];
                #pragma unroll
                for (int s = 0; s < K; s++) {
                    const float4* wv4 = (const float4*)(wrow + (r * K + s) * OCT);
                    float4 wa = wv4[0], wb = wv4[1];
                    float wv[OCT] = {wa.x, wa.y, wa.z, wa.w, wb.x, wb.y, wb.z, wb.w};
                    #pragma unroll
                    for (int o = 0; o < OCT; o++)
                        #pragma unroll
                        for (int j = 0; j < 8; j++)
                            acc[o][j] = fmaf(xwin[j + s], wv[o], acc[o][j]);
                }
            }
        }
    }

    // ---- epilogue: add class embedding, vector store ----
    const int yb = g_y[b];
    float ev[OCT];
    #pragma unroll
    for (int o = 0; o < OCT; o++)
        ev[o] = e[yb * OUT_C + oc0 + o];

    float* ob = out + (b * OUT_C + oc0) * NPIX + row * HW + colseg;
    #pragma unroll
    for (int o = 0; o < OCT; o++) {
        float4 v0, v1;
        v0.x = acc[o][0] + ev[o]; v0.y = acc[o][1] + ev[o];
        v0.z = acc[o][2] + ev[o]; v0.w = acc[o][3] + ev[o];
        v1.x = acc[o][4] + ev[o]; v1.y = acc[o][5] + ev[o];
        v1.z = acc[o][6] + ev[o]; v1.w = acc[o][7] + ev[o];
        ((float4*)(ob + o * NPIX))[0] = v0;
        ((float4*)(ob + o * NPIX))[1] = v1;
    }
}

extern "C" void kernel_launch(void* const* d_in, const int* in_sizes, int n_in,
                              void* d_out, int out_size) {
    const float* x = nullptr;
    const int*   yr = nullptr;
    const int*   ar = nullptr;
    const float* w[4] = {nullptr, nullptr, nullptr, nullptr};
    const float* e[4] = {nullptr, nullptr, nullptr, nullptr};
    int ne = 0, n64 = 0;

    for (int i = 0; i < n_in; i++) {
        int sz = in_sizes[i];
        const void* p = d_in[i];
        if      (sz == 16777216) x = (const float*)p;
        else if (sz == 64)       { if (n64++ == 0) yr = (const int*)p; else ar = (const int*)p; }
        else if (sz == 65536)    w[0] = (const float*)p;
        else if (sz == 589824)   w[1] = (const float*)p;
        else if (sz == 1638400)  w[2] = (const float*)p;
        else if (sz == 3211264)  w[3] = (const float*)p;
        else if (sz == 256000)   { if (ne < 4) e[ne++] = (const float*)p; }
    }

    decode_idx<<<1, 64>>>(yr, ar);

    float* out = (float*)d_out;
    dim3 grid(OUT_C / 8, NB);
    conv_branch<1><<<grid, 128>>>(x, w[0], e[0], out, 0);
    conv_branch<3><<<grid, 128>>>(x, w[1], e[1], out, 1);
    conv_branch<5><<<grid, 128>>>(x, w[2], e[2], out, 2);
    conv_branch<7><<<grid, 128>>>(x, w[3], e[3], out, 3);
}

// round 3
// speedup vs baseline: 1.1269x; 1.0585x over previous
#include <cuda_runtime.h>

#define IN_C   256
#define OUT_C  256
#define HW     32
#define NB     64
#define NPIX   (HW * HW)

typedef unsigned long long u64;

__device__ __forceinline__ u64 pack2(float x, float y) {
    u64 r; asm("mov.b64 %0, {%1, %2};" : "=l"(r) : "f"(x), "f"(y)); return r;
}
__device__ __forceinline__ u64 ffma2(u64 a, u64 b, u64 c) {
    u64 d; asm("fma.rn.f32x2 %0, %1, %2, %3;" : "=l"(d) : "l"(a), "l"(b), "l"(c)); return d;
}
__device__ __forceinline__ float2 unpack2(u64 v) {
    float2 f; asm("mov.b64 {%0, %1}, %2;" : "=f"(f.x), "=f"(f.y) : "l"(v)); return f;
}

__device__ int g_y[NB];
__device__ int g_arc[NB];

// Normalize y / sample_arc (int32 or int64) to int32.
__global__ void decode_idx(const int* __restrict__ yr, const int* __restrict__ ar) {
    __shared__ int is64;
    int t = threadIdx.x;
    if (t == 0) {
        int acc = 0;
        for (int i = 1; i < NB; i += 2) acc |= yr[i];
        is64 = (acc == 0) ? 1 : 0;
    }
    __syncthreads();
    if (t < NB) {
        int stride = is64 ? 2 : 1;
        g_y[t]   = yr[t * stride];
        g_arc[t] = ar[t * stride];
    }
}

// Direct conv with packed fp32x2 FMA.
// Block: 128 threads, 8 output channels, full 32x32 image.
// Thread: row = tid>>2, 8 contiguous pixels at colseg=(tid&3)*8.
// Accumulators: 4 oc-pairs x 8 pixels, each a packed f32x2 (oc 2o, 2o+1).
// Per (ic,r): 12-wide x window loaded once, packed (x,x) once, reused for
// all s and oc-pairs. Per (r,s): 4 LDS.64 of packed weight pairs + 32 FFMA2.
template<int K>
__global__ void __launch_bounds__(128, 4) conv_branch(
    const float* __restrict__ x, const float* __restrict__ w,
    const float* __restrict__ e, float* __restrict__ out, int branch)
{
    constexpr int PAD = K / 2;
    constexpr int PH  = HW + 2 * PAD;
    constexpr int RS  = (PH % 2 == 0) ? PH + 1 : PH;   // odd stride: conflict-free
    constexpr int ICB = 4;
    constexpr int OCT = 8;
    constexpr int WIN = 8 + K - 1;

    const int b = blockIdx.y;
    if (g_arc[b] != branch) return;
    const int oc0 = blockIdx.x * OCT;

    __shared__ __align__(16) float xs[ICB * PH * RS];
    __shared__ __align__(16) float ws[ICB * K * K * OCT];

    const int tid    = threadIdx.x;
    const int row    = tid >> 2;
    const int colseg = (tid & 3) * 8;

    u64 acc2[4][8];
    #pragma unroll
    for (int op = 0; op < 4; op++)
        #pragma unroll
        for (int j = 0; j < 8; j++)
            acc2[op][j] = 0ULL;

    const float* xb = x + (b * IN_C) * NPIX;

    #pragma unroll 1
    for (int ic0 = 0; ic0 < IN_C; ic0 += ICB) {
        __syncthreads();
        // ---- stage x tiles (zero halo) ----
        #pragma unroll 4
        for (int idx = tid; idx < ICB * PH * PH; idx += 128) {
            int ic  = idx / (PH * PH);
            int rem = idx - ic * (PH * PH);
            int ph  = rem / PH;
            int pw  = rem - ph * PH;
            int h  = ph - PAD;
            int wc = pw - PAD;
            float v = 0.0f;
            if ((unsigned)h < HW && (unsigned)wc < HW)
                v = xb[(ic0 + ic) * NPIX + h * HW + wc];
            xs[ic * (PH * RS) + ph * RS + pw] = v;
        }
        // ---- stage weights, layout [ic][rs][oc] ----
        #pragma unroll 4
        for (int idx = tid; idx < ICB * K * K * OCT; idx += 128) {
            int ic  = idx / (K * K * OCT);
            int rem = idx - ic * (K * K * OCT);
            int rs  = rem / OCT;
            int o   = rem - rs * OCT;
            ws[idx] = w[((oc0 + o) * IN_C + ic0 + ic) * (K * K) + rs];
        }
        __syncthreads();

        // ---- compute ----
        #pragma unroll 1
        for (int ic = 0; ic < ICB; ic++) {
            const float* xrow0 = xs + ic * (PH * RS) + row * RS + colseg;
            const float* wrow  = ws + ic * (K * K * OCT);
            #pragma unroll 1
            for (int r = 0; r < K; r++) {
                const float* xr = xrow0 + r * RS;
                u64 xp[WIN];
                #pragma unroll
                for (int j = 0; j < WIN; j++) {
                    float v = xr[j];
                    xp[j] = pack2(v, v);
                }
                #pragma unroll
                for (int s = 0; s < K; s++) {
                    const u64* wp = (const u64*)(wrow + (r * K + s) * OCT);
                    u64 w0 = wp[0], w1 = wp[1], w2 = wp[2], w3 = wp[3];
                    #pragma unroll
                    for (int j = 0; j < 8; j++) {
                        acc2[0][j] = ffma2(xp[j + s], w0, acc2[0][j]);
                        acc2[1][j] = ffma2(xp[j + s], w1, acc2[1][j]);
                        acc2[2][j] = ffma2(xp[j + s], w2, acc2[2][j]);
                        acc2[3][j] = ffma2(xp[j + s], w3, acc2[3][j]);
                    }
                }
            }
        }
    }

    // ---- epilogue: add class embedding, vector store ----
    const int yb = g_y[b];
    const float* ebase = e + yb * OUT_C + oc0;

    float* ob = out + (b * OUT_C + oc0) * NPIX + row * HW + colseg;
    #pragma unroll
    for (int op = 0; op < 4; op++) {
        float e0 = ebase[2 * op];
        float e1 = ebase[2 * op + 1];
        float r0[8], r1[8];
        #pragma unroll
        for (int j = 0; j < 8; j++) {
            float2 v = unpack2(acc2[op][j]);
            r0[j] = v.x + e0;
            r1[j] = v.y + e1;
        }
        float4* p0 = (float4*)(ob + (2 * op) * NPIX);
        float4* p1 = (float4*)(ob + (2 * op + 1) * NPIX);
        p0[0] = make_float4(r0[0], r0[1], r0[2], r0[3]);
        p0[1] = make_float4(r0[4], r0[5], r0[6], r0[7]);
        p1[0] = make_float4(r1[0], r1[1], r1[2], r1[3]);
        p1[1] = make_float4(r1[4], r1[5], r1[6], r1[7]);
    }
}

extern "C" void kernel_launch(void* const* d_in, const int* in_sizes, int n_in,
                              void* d_out, int out_size) {
    const float* x = nullptr;
    const int*   yr = nullptr;
    const int*   ar = nullptr;
    const float* w[4] = {nullptr, nullptr, nullptr, nullptr};
    const float* e[4] = {nullptr, nullptr, nullptr, nullptr};
    int ne = 0, n64 = 0;

    for (int i = 0; i < n_in; i++) {
        int sz = in_sizes[i];
        const void* p = d_in[i];
        if      (sz == 16777216) x = (const float*)p;
        else if (sz == 64)       { if (n64++ == 0) yr = (const int*)p; else ar = (const int*)p; }
        else if (sz == 65536)    w[0] = (const float*)p;
        else if (sz == 589824)   w[1] = (const float*)p;
        else if (sz == 1638400)  w[2] = (const float*)p;
        else if (sz == 3211264)  w[3] = (const float*)p;
        else if (sz == 256000)   { if (ne < 4) e[ne++] = (const float*)p; }
    }

    decode_idx<<<1, 64>>>(yr, ar);

    float* out = (float*)d_out;
    dim3 grid(OUT_C / 8, NB);
    conv_branch<1><<<grid, 128>>>(x, w[0], e[0], out, 0);
    conv_branch<3><<<grid, 128>>>(x, w[1], e[1], out, 1);
    conv_branch<5><<<grid, 128>>>(x, w[2], e[2], out, 2);
    conv_branch<7><<<grid, 128>>>(x, w[3], e[3], out, 3);
}

// round 6
// speedup vs baseline: 3.4040x; 3.0208x over previous
#include <cuda_runtime.h>
#include <cstdint>

typedef uint32_t u32;

#define IN_C  256
#define OUT_C 256
#define HW    32
#define NB    64
#define NPIX  1024

__device__ int g_y[NB];
__device__ int g_arc[NB];
__device__ float g_wt2[5505024];               // [branch][rs][oc][c], tf32-rounded
__device__ float g_x2[NB * IN_C * NPIX];       // tf32-rounded x

// ---------------- helpers ----------------
__device__ __forceinline__ u32 smem_u32(const void* p) {
    u32 a; asm("{ .reg .u64 t; cvta.to.shared.u64 t, %1; cvt.u32.u64 %0, t; }" : "=r"(a) : "l"(p));
    return a;
}
__device__ __forceinline__ float to_tf32(float v) {
    float o; asm("cvt.rna.tf32.f32 %0, %1;" : "=f"(o) : "f"(v)); return o;
}
__device__ __forceinline__ void cpa16(u32 dst, const void* src, bool valid) {
    int sz = valid ? 16 : 0;
    asm volatile("cp.async.ca.shared.global [%0], [%1], 16, %2;"
                 :: "r"(dst), "l"(src), "r"(sz) : "memory");
}
#define CP_COMMIT() asm volatile("cp.async.commit_group;" ::: "memory")
#define CP_WAIT(n)  asm volatile("cp.async.wait_group %0;" :: "n"(n) : "memory")

__device__ __forceinline__ void mma_tf32(float* c, u32 a0, u32 a1, u32 a2, u32 a3,
                                         u32 b0, u32 b1) {
    asm volatile("mma.sync.aligned.m16n8k8.row.col.f32.tf32.tf32.f32 "
                 "{%0,%1,%2,%3}, {%4,%5,%6,%7}, {%8,%9}, {%0,%1,%2,%3};"
                 : "+f"(c[0]), "+f"(c[1]), "+f"(c[2]), "+f"(c[3])
                 : "r"(a0), "r"(a1), "r"(a2), "r"(a3), "r"(b0), "r"(b1));
}

// ---------------- prep kernels ----------------
__global__ void decode_idx(const int* __restrict__ yr, const int* __restrict__ ar) {
    __shared__ int is64;
    int t = threadIdx.x;
    if (t == 0) {
        int acc = 0;
        for (int i = 1; i < NB; i += 2) acc |= yr[i];
        is64 = (acc == 0) ? 1 : 0;
    }
    __syncthreads();
    if (t < NB) {
        int st = is64 ? 2 : 1;
        g_y[t]   = yr[t * st];
        g_arc[t] = ar[t * st];
    }
}

__global__ void transform_w(const float* __restrict__ w0, const float* __restrict__ w1,
                            const float* __restrict__ w2, const float* __restrict__ w3) {
    int br = blockIdx.y;
    const float* w = (br == 0) ? w0 : (br == 1) ? w1 : (br == 2) ? w2 : w3;
    int k = 2 * br + 1, kk = k * k;
    int off = (br == 0) ? 0 : (br == 1) ? 65536 : (br == 2) ? 655360 : 2293760;
    int total = kk * OUT_C * IN_C;
    for (int idx = blockIdx.x * 256 + threadIdx.x; idx < total; idx += gridDim.x * 256) {
        int rs = idx % kk; int t = idx / kk;
        int c = t & 255; int oc = t >> 8;
        g_wt2[off + (rs * OUT_C + oc) * IN_C + c] = to_tf32(w[idx]);
    }
}

__global__ void transform_x(const float* __restrict__ x) {
    for (int i = blockIdx.x * 256 + threadIdx.x; i < NB * IN_C * NPIX; i += gridDim.x * 256)
        g_x2[i] = to_tf32(x[i]);
}

// ---------------- main kernel ----------------
// CTA: (b, oct, pband). 256 thr = 8 warps (2m x 4n), warp tile 64oc x 64pix.
// CTA tile: 128 oc x 256 pix (8 image rows).
// Smem: As[2][128][36] double-buffered weights; Xs[32][R][40] haloed x tile.
#define AS_STRIDE 36
#define AS_FLOATS (128 * AS_STRIDE)
#define SMEM_FLOATS (2 * AS_FLOATS + 32 * (14 * 40 + 8))
#define SMEM_BYTES  (SMEM_FLOATS * 4)

__global__ void __launch_bounds__(256, 1)
conv_mma(const float* __restrict__ e0_, const float* __restrict__ e1_,
         const float* __restrict__ e2_, const float* __restrict__ e3_,
         float* __restrict__ out)
{
    extern __shared__ float smem[];
    const u32 sbase = smem_u32(smem);

    const int tid  = threadIdx.x;
    const int wid  = tid >> 5, lane = tid & 31;
    const int g    = lane >> 2, t = lane & 3;
    const int wm   = wid >> 2;           // 0..1  (m warps)
    const int wn   = wid & 3;            // 0..3  (n warps)

    const int b     = blockIdx.x >> 3;
    const int oct   = (blockIdx.x >> 2) & 1;
    const int pband = blockIdx.x & 3;

    const int br = g_arc[b];
    const int k  = 2 * br + 1, pk = br, kk = k * k;
    const int R  = 8 + k - 1;
    const int CSTf = R * 40 + 8;         // channel stride in Xs (floats)
    const float* eptr = (br == 0) ? e0_ : (br == 1) ? e1_ : (br == 2) ? e2_ : e3_;
    const int woff = (br == 0) ? 0 : (br == 1) ? 65536 : (br == 2) ? 655360 : 2293760;

    float* As[2] = { smem, smem + AS_FLOATS };
    float* Xs    = smem + 2 * AS_FLOATS;
    const u32 uAs[2] = { sbase, sbase + AS_FLOATS * 4 };
    const u32 uXs    = sbase + 2 * AS_FLOATS * 4;

    // B-fragment pixel bases per n-tile (row_p*40 + col_p)
    int pixbase[8];
    #pragma unroll
    for (int nt = 0; nt < 8; nt++) {
        int p = wn * 64 + nt * 8 + g;
        pixbase[nt] = (p >> 5) * 40 + (p & 31);
    }

    float acc[4][8][4];
    #pragma unroll
    for (int mt = 0; mt < 4; mt++)
        #pragma unroll
        for (int nt = 0; nt < 8; nt++)
            #pragma unroll
            for (int q = 0; q < 4; q++)
                acc[mt][nt][q] = 0.0f;

    const int h0 = pband * 8 - pk;       // image row of Xs row 0
    const int xchunk_f4 = 32 * R * 10;   // float4 count of Xs tile

    #pragma unroll 1
    for (int chunk = 0; chunk < 8; chunk++) {
        const int ic0 = chunk * 32;
        __syncthreads();   // protect Xs/As from previous chunk's readers

        // ---- stage Xs (haloed x tile, zero-filled OOB) ----
        #pragma unroll 1
        for (int id = tid; id < xchunk_f4; id += 256) {
            int c    = id / (R * 10);
            int rem  = id - c * (R * 10);
            int rowi = rem / 10;
            int c4   = rem - rowi * 10;
            int h    = h0 + rowi;
            int iw0  = c4 * 4 - 4;
            bool valid = ((unsigned)h < HW) && ((unsigned)iw0 < HW);
            const float* src = g_x2
                + ((size_t)(b * IN_C + ic0 + c) * HW + (valid ? h : 0)) * HW
                + (valid ? iw0 : 0);
            cpa16(uXs + (u32)(c * CSTf + rowi * 40 + c4 * 4) * 4, src, valid);
        }
        // ---- stage As for rs=0 ----
        {
            const float* wsrc = g_wt2 + woff + (size_t)oct * 128 * IN_C + ic0;
            #pragma unroll
            for (int j = 0; j < 4; j++) {
                int id = j * 256 + tid;
                int oc = id >> 3, c4 = id & 7;
                cpa16(uAs[0] + (u32)(oc * AS_STRIDE + c4 * 4) * 4,
                      wsrc + (size_t)oc * IN_C + c4 * 4, true);
            }
        }
        CP_COMMIT();

        int r = 0, s = 0;
        #pragma unroll 1
        for (int rs = 0; rs < kk; rs++) {
            const int buf = rs & 1;
            if (rs + 1 < kk) {
                const float* wsrc = g_wt2 + woff + (size_t)(rs + 1) * OUT_C * IN_C
                                  + (size_t)oct * 128 * IN_C + ic0;
                #pragma unroll
                for (int j = 0; j < 4; j++) {
                    int id = j * 256 + tid;
                    int oc = id >> 3, c4 = id & 7;
                    cpa16(uAs[buf ^ 1] + (u32)(oc * AS_STRIDE + c4 * 4) * 4,
                          wsrc + (size_t)oc * IN_C + c4 * 4, true);
                }
                CP_COMMIT();
                CP_WAIT(1);
            } else {
                CP_WAIT(0);
            }
            __syncthreads();

            // ---- compute: 4 k8-steps over this 32-channel chunk ----
            const float* Ab = As[buf] + (wm * 64 + g) * AS_STRIDE + t;
            const float* Bb = Xs + r * 40 + (s - pk + 4) + t * CSTf;
            #pragma unroll
            for (int ck = 0; ck < 4; ck++) {
                const int c0 = ck * 8;
                u32 ra[4][4];
                #pragma unroll
                for (int mt = 0; mt < 4; mt++) {
                    const float* ap = Ab + mt * 16 * AS_STRIDE + c0;
                    ra[mt][0] = __float_as_uint(ap[0]);
                    ra[mt][1] = __float_as_uint(ap[8 * AS_STRIDE]);
                    ra[mt][2] = __float_as_uint(ap[4]);
                    ra[mt][3] = __float_as_uint(ap[8 * AS_STRIDE + 4]);
                }
                u32 rb[8][2];
                const float* bp = Bb + c0 * CSTf;
                #pragma unroll
                for (int nt = 0; nt < 8; nt++) {
                    rb[nt][0] = __float_as_uint(bp[pixbase[nt]]);
                    rb[nt][1] = __float_as_uint(bp[4 * CSTf + pixbase[nt]]);
                }
                #pragma unroll
                for (int mt = 0; mt < 4; mt++)
                    #pragma unroll
                    for (int nt = 0; nt < 8; nt++)
                        mma_tf32(acc[mt][nt], ra[mt][0], ra[mt][1], ra[mt][2], ra[mt][3],
                                 rb[nt][0], rb[nt][1]);
            }
            __syncthreads();   // before next overwrite of As[buf^1]
            if (++s == k) { s = 0; r++; }
        }
    }

    // ---- epilogue: += class embedding, store ----
    const int yb = g_y[b];
    const int ocg = oct * 128 + wm * 64;
    #pragma unroll
    for (int mt = 0; mt < 4; mt++) {
        int oc_lo = ocg + mt * 16 + g;
        int oc_hi = oc_lo + 8;
        float ev_lo = eptr[yb * OUT_C + oc_lo];
        float ev_hi = eptr[yb * OUT_C + oc_hi];
        float* base_lo = out + (size_t)(b * OUT_C + oc_lo) * NPIX + pband * 256;
        float* base_hi = out + (size_t)(b * OUT_C + oc_hi) * NPIX + pband * 256;
        #pragma unroll
        for (int nt = 0; nt < 8; nt++) {
            int p = wn * 64 + nt * 8 + 2 * t;
            float2 vlo = make_float2(acc[mt][nt][0] + ev_lo, acc[mt][nt][1] + ev_lo);
            float2 vhi = make_float2(acc[mt][nt][2] + ev_hi, acc[mt][nt][3] + ev_hi);
            *(float2*)(base_lo + p) = vlo;
            *(float2*)(base_hi + p) = vhi;
        }
    }
}

// ---------------- launcher ----------------
extern "C" void kernel_launch(void* const* d_in, const int* in_sizes, int n_in,
                              void* d_out, int out_size) {
    const float* x = nullptr;
    const int *yr = nullptr, *ar = nullptr;
    const float* w[4] = {nullptr, nullptr, nullptr, nullptr};
    const float* e[4] = {nullptr, nullptr, nullptr, nullptr};
    int ne = 0, n64 = 0;

    for (int i = 0; i < n_in; i++) {
        int sz = in_sizes[i];
        const void* p = d_in[i];
        if      (sz == 16777216) x = (const float*)p;
        else if (sz == 64)       { if (n64++ == 0) yr = (const int*)p; else ar = (const int*)p; }
        else if (sz == 65536)    w[0] = (const float*)p;
        else if (sz == 589824)   w[1] = (const float*)p;
        else if (sz == 1638400)  w[2] = (const float*)p;
        else if (sz == 3211264)  w[3] = (const float*)p;
        else if (sz == 256000)   { if (ne < 4) e[ne++] = (const float*)p; }
    }

    cudaFuncSetAttribute(conv_mma, cudaFuncAttributeMaxDynamicSharedMemorySize, SMEM_BYTES);

    decode_idx<<<1, 64>>>(yr, ar);
    transform_w<<<dim3(1024, 4), 256>>>(w[0], w[1], w[2], w[3]);
    transform_x<<<2048, 256>>>(x);
    conv_mma<<<512, 256, SMEM_BYTES>>>(e[0], e[1], e[2], e[3], (float*)d_out);
}

// round 8
// speedup vs baseline: 3.5680x; 1.0482x over previous
#include <cuda_runtime.h>
#include <cstdint>

typedef uint32_t u32;

#define IN_C  256
#define OUT_C 256
#define HW    32
#define NB    64
#define NPIX  1024

__device__ int g_y[NB];
__device__ int g_arc[NB];
__device__ int g_order[NB];
__device__ float g_wt2[5505024];               // [branch][rs][oc][c], tf32-rounded
__device__ float g_x2[NB * IN_C * NPIX];       // tf32-rounded x

// ---------------- helpers ----------------
__device__ __forceinline__ u32 smem_u32(const void* p) {
    u32 a; asm("{ .reg .u64 t; cvta.to.shared.u64 t, %1; cvt.u32.u64 %0, t; }" : "=r"(a) : "l"(p));
    return a;
}
__device__ __forceinline__ float to_tf32(float v) {
    float o; asm("cvt.rna.tf32.f32 %0, %1;" : "=f"(o) : "f"(v)); return o;
}
__device__ __forceinline__ void cpa16(u32 dst, const void* src, bool valid) {
    int sz = valid ? 16 : 0;
    asm volatile("cp.async.ca.shared.global [%0], [%1], 16, %2;"
                 :: "r"(dst), "l"(src), "r"(sz) : "memory");
}
#define CP_COMMIT() asm volatile("cp.async.commit_group;" ::: "memory")
#define CP_WAIT(n)  asm volatile("cp.async.wait_group %0;" :: "n"(n) : "memory")

__device__ __forceinline__ void mma_tf32(float* c, u32 a0, u32 a1, u32 a2, u32 a3,
                                         u32 b0, u32 b1) {
    asm volatile("mma.sync.aligned.m16n8k8.row.col.f32.tf32.tf32.f32 "
                 "{%0,%1,%2,%3}, {%4,%5,%6,%7}, {%8,%9}, {%0,%1,%2,%3};"
                 : "+f"(c[0]), "+f"(c[1]), "+f"(c[2]), "+f"(c[3])
                 : "r"(a0), "r"(a1), "r"(a2), "r"(a3), "r"(b0), "r"(b1));
}

// ---------------- prep kernels ----------------
__global__ void decode_idx(const int* __restrict__ yr, const int* __restrict__ ar) {
    __shared__ int is64;
    int t = threadIdx.x;
    if (t == 0) {
        int acc = 0;
        for (int i = 1; i < NB; i += 2) acc |= yr[i];
        is64 = (acc == 0) ? 1 : 0;
    }
    __syncthreads();
    if (t < NB) {
        int st = is64 ? 2 : 1;
        g_y[t]   = yr[t * st];
        g_arc[t] = ar[t * st];
    }
    __syncthreads();
    if (t == 0) {
        // heavy-branch-first image order
        int n = 0;
        for (int br = 3; br >= 0; br--)
            for (int i = 0; i < NB; i++)
                if (g_arc[i] == br) g_order[n++] = i;
    }
}

__global__ void transform_w(const float* __restrict__ w0, const float* __restrict__ w1,
                            const float* __restrict__ w2, const float* __restrict__ w3) {
    int br = blockIdx.y;
    const float* w = (br == 0) ? w0 : (br == 1) ? w1 : (br == 2) ? w2 : w3;
    int k = 2 * br + 1, kk = k * k;
    int off = (br == 0) ? 0 : (br == 1) ? 65536 : (br == 2) ? 655360 : 2293760;
    int total = kk * OUT_C * IN_C;
    for (int idx = blockIdx.x * 256 + threadIdx.x; idx < total; idx += gridDim.x * 256) {
        int rs = idx % kk; int t = idx / kk;
        int c = t & 255; int oc = t >> 8;
        g_wt2[off + (rs * OUT_C + oc) * IN_C + c] = to_tf32(w[idx]);
    }
}

__global__ void transform_x(const float* __restrict__ x) {
    for (int i = blockIdx.x * 256 + threadIdx.x; i < NB * IN_C * NPIX; i += gridDim.x * 256)
        g_x2[i] = to_tf32(x[i]);
}

// ---------------- main kernel ----------------
// CTA: (b, oct, pband). 256 thr = 8 warps (2m x 4n), warp tile 64oc x 64pix.
// Pipeline per step i: wait(own g_i) -> syncthreads (publish g_i, retire
// readers of buffer (i+1)&1) -> issue g_{i+1} -> compute step i.
#define AS_STRIDE 36
#define AS_FLOATS (128 * AS_STRIDE)
#define XS_FLOATS_MAX (32 * (14 * 40 + 8))
#define SMEM_FLOATS (2 * AS_FLOATS + 2 * XS_FLOATS_MAX)
#define SMEM_BYTES  (SMEM_FLOATS * 4)

__global__ void __launch_bounds__(256, 1)
conv_mma(const float* __restrict__ e0_, const float* __restrict__ e1_,
         const float* __restrict__ e2_, const float* __restrict__ e3_,
         float* __restrict__ out)
{
    extern __shared__ float smem[];
    const u32 sbase = smem_u32(smem);

    const int tid  = threadIdx.x;
    const int wid  = tid >> 5, lane = tid & 31;
    const int g    = lane >> 2, t = lane & 3;
    const int wm   = wid >> 2;
    const int wn   = wid & 3;

    const int b     = g_order[blockIdx.x >> 3];
    const int oct   = (blockIdx.x >> 2) & 1;
    const int pband = blockIdx.x & 3;

    const int br = g_arc[b];
    const int k  = 2 * br + 1, pk = br, kk = k * k;
    const int R  = 8 + k - 1;
    const int CSTf = R * 40 + 8;                 // channel stride in Xs (floats)
    const float* eptr = (br == 0) ? e0_ : (br == 1) ? e1_ : (br == 2) ? e2_ : e3_;
    const int woff = (br == 0) ? 0 : (br == 1) ? 65536 : (br == 2) ? 655360 : 2293760;

    float* As[2] = { smem, smem + AS_FLOATS };
    float* Xs[2] = { smem + 2 * AS_FLOATS, smem + 2 * AS_FLOATS + 32 * CSTf };
    const u32 uAs[2] = { sbase, sbase + AS_FLOATS * 4 };
    const u32 uXs[2] = { sbase + 2 * AS_FLOATS * 4,
                         sbase + (2 * AS_FLOATS + 32 * CSTf) * 4 };

    int pixbase[8];
    #pragma unroll
    for (int nt = 0; nt < 8; nt++) {
        int p = wn * 64 + nt * 8 + g;
        pixbase[nt] = (p >> 5) * 40 + (p & 31);
    }

    float acc[4][8][4];
    #pragma unroll
    for (int mt = 0; mt < 4; mt++)
        #pragma unroll
        for (int nt = 0; nt < 8; nt++)
            #pragma unroll
            for (int q = 0; q < 4; q++)
                acc[mt][nt][q] = 0.0f;

    const int h0 = pband * 8 - pk;
    const int xf4 = 32 * R * 10;
    const float* wctabase = g_wt2 + woff + (size_t)oct * 128 * IN_C;

    #define ISSUE_A(chunk_, rs_, ub_) do { \
        const float* wsrc = wctabase + (size_t)(rs_) * OUT_C * IN_C + ((chunk_) << 5); \
        _Pragma("unroll") \
        for (int j = 0; j < 4; j++) { \
            int id = j * 256 + tid; \
            int oc = id >> 3, c4 = id & 7; \
            cpa16((ub_) + (u32)(oc * AS_STRIDE + c4 * 4) * 4, \
                  wsrc + (size_t)oc * IN_C + c4 * 4, true); \
        } \
    } while (0)

    #define ISSUE_X(chunk_, ub_) do { \
        const int ic0_ = (chunk_) << 5; \
        _Pragma("unroll 1") \
        for (int id = tid; id < xf4; id += 256) { \
            int c    = id / (R * 10); \
            int rem  = id - c * (R * 10); \
            int rowi = rem / 10; \
            int c4   = rem - rowi * 10; \
            int h    = h0 + rowi; \
            int iw0  = c4 * 4 - 4; \
            bool valid = ((unsigned)h < HW) && ((unsigned)iw0 < HW); \
            const float* src = g_x2 \
                + ((size_t)(b * IN_C + ic0_ + c) * HW + (valid ? h : 0)) * HW \
                + (valid ? iw0 : 0); \
            cpa16((ub_) + (u32)(c * CSTf + rowi * 40 + c4 * 4) * 4, src, valid); \
        } \
    } while (0)

    const int T = 8 * kk;

    // ---- prologue: stage step 0 (X chunk0 + A rs0) ----
    ISSUE_X(0, uXs[0]);
    ISSUE_A(0, 0, uAs[0]);
    CP_COMMIT();

    int r = 0, s = 0;
    #pragma unroll 1
    for (int i = 0; i < T; i++) {
        const int chunk = i / kk;
        CP_WAIT(0);          // own copies of group i complete
        __syncthreads();     // publish group i to all; retire readers of other buffers
        if (i + 1 < T) {
            const int i1 = i + 1;
            const int c1 = i1 / kk, rs1 = i1 - c1 * kk;
            if (rs1 == 0) ISSUE_X(c1, uXs[c1 & 1]);
            ISSUE_A(c1, rs1, uAs[i1 & 1]);
            CP_COMMIT();
        }

        // ---- compute step i (overlaps group i+1 copies) ----
        const float* Ab = As[i & 1] + (wm * 64 + g) * AS_STRIDE + t;
        const float* Bb = Xs[chunk & 1] + r * 40 + (s - pk + 4) + t * CSTf;
        #pragma unroll
        for (int ck = 0; ck < 4; ck++) {
            const int c0 = ck * 8;
            u32 ra[4][4];
            #pragma unroll
            for (int mt = 0; mt < 4; mt++) {
                const float* ap = Ab + mt * 16 * AS_STRIDE + c0;
                ra[mt][0] = __float_as_uint(ap[0]);
                ra[mt][1] = __float_as_uint(ap[8 * AS_STRIDE]);
                ra[mt][2] = __float_as_uint(ap[4]);
                ra[mt][3] = __float_as_uint(ap[8 * AS_STRIDE + 4]);
            }
            u32 rb[8][2];
            const float* bp = Bb + c0 * CSTf;
            #pragma unroll
            for (int nt = 0; nt < 8; nt++) {
                rb[nt][0] = __float_as_uint(bp[pixbase[nt]]);
                rb[nt][1] = __float_as_uint(bp[4 * CSTf + pixbase[nt]]);
            }
            #pragma unroll
            for (int mt = 0; mt < 4; mt++)
                #pragma unroll
                for (int nt = 0; nt < 8; nt++)
                    mma_tf32(acc[mt][nt], ra[mt][0], ra[mt][1], ra[mt][2], ra[mt][3],
                             rb[nt][0], rb[nt][1]);
        }
        if (++s == k) { s = 0; if (++r == k) r = 0; }
    }

    // ---- epilogue: += class embedding, store ----
    const int yb = g_y[b];
    const int ocg = oct * 128 + wm * 64;
    #pragma unroll
    for (int mt = 0; mt < 4; mt++) {
        int oc_lo = ocg + mt * 16 + g;
        int oc_hi = oc_lo + 8;
        float ev_lo = eptr[yb * OUT_C + oc_lo];
        float ev_hi = eptr[yb * OUT_C + oc_hi];
        float* base_lo = out + (size_t)(b * OUT_C + oc_lo) * NPIX + pband * 256;
        float* base_hi = out + (size_t)(b * OUT_C + oc_hi) * NPIX + pband * 256;
        #pragma unroll
        for (int nt = 0; nt < 8; nt++) {
            int p = wn * 64 + nt * 8 + 2 * t;
            float2 vlo = make_float2(acc[mt][nt][0] + ev_lo, acc[mt][nt][1] + ev_lo);
            float2 vhi = make_float2(acc[mt][nt][2] + ev_hi, acc[mt][nt][3] + ev_hi);
            *(float2*)(base_lo + p) = vlo;
            *(float2*)(base_hi + p) = vhi;
        }
    }
}

// ---------------- launcher ----------------
extern "C" void kernel_launch(void* const* d_in, const int* in_sizes, int n_in,
                              void* d_out, int out_size) {
    const float* x = nullptr;
    const int *yr = nullptr, *ar = nullptr;
    const float* w[4] = {nullptr, nullptr, nullptr, nullptr};
    const float* e[4] = {nullptr, nullptr, nullptr, nullptr};
    int ne = 0, n64 = 0;

    for (int i = 0; i < n_in; i++) {
        int sz = in_sizes[i];
        const void* p = d_in[i];
        if      (sz == 16777216) x = (const float*)p;
        else if (sz == 64)       { if (n64++ == 0) yr = (const int*)p; else ar = (const int*)p; }
        else if (sz == 65536)    w[0] = (const float*)p;
        else if (sz == 589824)   w[1] = (const float*)p;
        else if (sz == 1638400)  w[2] = (const float*)p;
        else if (sz == 3211264)  w[3] = (const float*)p;
        else if (sz == 256000)   { if (ne < 4) e[ne++] = (const float*)p; }
    }

    cudaFuncSetAttribute(conv_mma, cudaFuncAttributeMaxDynamicSharedMemorySize, SMEM_BYTES);

    decode_idx<<<1, 64>>>(yr, ar);
    transform_w<<<dim3(1024, 4), 256>>>(w[0], w[1], w[2], w[3]);
    transform_x<<<2048, 256>>>(x);
    conv_mma<<<512, 256, SMEM_BYTES>>>(e[0], e[1], e[2], e[3], (float*)d_out);
}

// round 9
// speedup vs baseline: 7.6189x; 2.1353x over previous
#include <cuda_runtime.h>
#include <cuda_fp16.h>
#include <cstdint>

typedef uint32_t u32;

#define IN_C  256
#define OUT_C 256
#define HW    32
#define NB    64
#define NPIX  1024

__device__ int g_y[NB];
__device__ int g_arc[NB];
__device__ int g_order[NB];
__device__ __half  g_wh[5505024];            // [branch][rs][oc][c], fp16
__device__ __half2 g_xh[NB * 128 * NPIX];    // [b][cpair][pix], channels (2cp,2cp+1)

// ---------------- helpers ----------------
__device__ __forceinline__ u32 smem_u32(const void* p) {
    u32 a; asm("{ .reg .u64 t; cvta.to.shared.u64 t, %1; cvt.u32.u64 %0, t; }" : "=r"(a) : "l"(p));
    return a;
}
__device__ __forceinline__ void cpa16(u32 dst, const void* src, bool valid) {
    int sz = valid ? 16 : 0;
    asm volatile("cp.async.ca.shared.global [%0], [%1], 16, %2;"
                 :: "r"(dst), "l"(src), "r"(sz) : "memory");
}
#define CP_COMMIT() asm volatile("cp.async.commit_group;" ::: "memory")
#define CP_WAIT(n)  asm volatile("cp.async.wait_group %0;" :: "n"(n) : "memory")

__device__ __forceinline__ void mma_f16(float* c, u32 a0, u32 a1, u32 a2, u32 a3,
                                        u32 b0, u32 b1) {
    asm volatile("mma.sync.aligned.m16n8k16.row.col.f32.f16.f16.f32 "
                 "{%0,%1,%2,%3}, {%4,%5,%6,%7}, {%8,%9}, {%0,%1,%2,%3};"
                 : "+f"(c[0]), "+f"(c[1]), "+f"(c[2]), "+f"(c[3])
                 : "r"(a0), "r"(a1), "r"(a2), "r"(a3), "r"(b0), "r"(b1));
}

// ---------------- prep kernels ----------------
__global__ void decode_idx(const int* __restrict__ yr, const int* __restrict__ ar) {
    __shared__ int is64;
    int t = threadIdx.x;
    if (t == 0) {
        int acc = 0;
        for (int i = 1; i < NB; i += 2) acc |= yr[i];
        is64 = (acc == 0) ? 1 : 0;
    }
    __syncthreads();
    if (t < NB) {
        int st = is64 ? 2 : 1;
        g_y[t]   = yr[t * st];
        g_arc[t] = ar[t * st];
    }
    __syncthreads();
    if (t == 0) {
        int n = 0;
        for (int br = 3; br >= 0; br--)
            for (int i = 0; i < NB; i++)
                if (g_arc[i] == br) g_order[n++] = i;
    }
}

__global__ void transform_w(const float* __restrict__ w0, const float* __restrict__ w1,
                            const float* __restrict__ w2, const float* __restrict__ w3) {
    int br = blockIdx.y;
    const float* w = (br == 0) ? w0 : (br == 1) ? w1 : (br == 2) ? w2 : w3;
    int k = 2 * br + 1, kk = k * k;
    int off = (br == 0) ? 0 : (br == 1) ? 65536 : (br == 2) ? 655360 : 2293760;
    int total = kk * OUT_C * IN_C;
    for (int idx = blockIdx.x * 256 + threadIdx.x; idx < total; idx += gridDim.x * 256) {
        int rs = idx % kk; int t = idx / kk;
        int c = t & 255; int oc = t >> 8;
        g_wh[off + (rs * OUT_C + oc) * IN_C + c] = __float2half_rn(w[idx]);
    }
}

__global__ void transform_x(const float* __restrict__ x) {
    int total = NB * 128 * NPIX;
    for (int i = blockIdx.x * 256 + threadIdx.x; i < total; i += gridDim.x * 256) {
        int pix = i & 1023;
        int cp  = (i >> 10) & 127;
        int b   = i >> 17;
        float v0 = x[(((b << 8) + 2 * cp + 0) << 10) + pix];
        float v1 = x[(((b << 8) + 2 * cp + 1) << 10) + pix];
        g_xh[i] = __floats2half2_rn(v0, v1);
    }
}

// ---------------- main kernel ----------------
// CTA: (b, oct, pband). 256 thr = 8 warps (2m x 4n), warp tile 64oc x 64pix.
// fp16 m16n8k16. A smem: [128 oc][40 halfs] (20-word rows, conflict-free).
// B smem: half2 [16 cpair][R][40], cpair stride CST2 = R*40+8 words.
#define AS_BYTES  (128 * 40 * 2)          // 10240 per buffer
#define XS_WORDS_MAX (16 * (14 * 40 + 8)) // 9088 words per buffer (R=14)
#define SMEM_BYTES (2 * AS_BYTES + 2 * XS_WORDS_MAX * 4)

__global__ void __launch_bounds__(256, 1)
conv_mma(const float* __restrict__ e0_, const float* __restrict__ e1_,
         const float* __restrict__ e2_, const float* __restrict__ e3_,
         float* __restrict__ out)
{
    extern __shared__ char smem[];
    const u32 sbase = smem_u32(smem);

    const int tid  = threadIdx.x;
    const int wid  = tid >> 5, lane = tid & 31;
    const int g    = lane >> 2, t = lane & 3;
    const int wm   = wid >> 2;
    const int wn   = wid & 3;

    const int b     = g_order[blockIdx.x >> 3];
    const int oct   = (blockIdx.x >> 2) & 1;
    const int pband = blockIdx.x & 3;

    const int br = g_arc[b];
    const int k  = 2 * br + 1, pk = br, kk = k * k;
    const int R  = 8 + k - 1;
    const int CST2 = R * 40 + 8;                 // cpair stride in words
    const int XS_BYTES = 16 * CST2 * 4;
    const float* eptr = (br == 0) ? e0_ : (br == 1) ? e1_ : (br == 2) ? e2_ : e3_;
    const int woff = (br == 0) ? 0 : (br == 1) ? 65536 : (br == 2) ? 655360 : 2293760;

    const u32 uAs[2] = { sbase, sbase + AS_BYTES };
    const u32 uXs[2] = { sbase + 2 * AS_BYTES, sbase + 2 * AS_BYTES + (u32)XS_BYTES };

    int pixbase[8];
    #pragma unroll
    for (int nt = 0; nt < 8; nt++) {
        int p = wn * 64 + nt * 8 + g;
        pixbase[nt] = (p >> 5) * 40 + (p & 31);
    }

    float acc[4][8][4];
    #pragma unroll
    for (int mt = 0; mt < 4; mt++)
        #pragma unroll
        for (int nt = 0; nt < 8; nt++)
            #pragma unroll
            for (int q = 0; q < 4; q++)
                acc[mt][nt][q] = 0.0f;

    const int h0 = pband * 8 - pk;
    const int xf4 = 16 * R * 10;                 // 16B copies per X tile
    const __half* wctabase = g_wh + woff + (size_t)oct * 128 * IN_C;

    #define ISSUE_A(chunk_, rs_, ub_) do { \
        const __half* wsrc = wctabase + (size_t)(rs_) * OUT_C * IN_C + ((chunk_) << 5); \
        _Pragma("unroll") \
        for (int j = 0; j < 2; j++) { \
            int id = j * 256 + tid; \
            int oc = id >> 2, c8 = id & 3; \
            cpa16((ub_) + (u32)(oc * 80 + c8 * 16), \
                  wsrc + (size_t)oc * IN_C + c8 * 8, true); \
        } \
    } while (0)

    #define ISSUE_X(chunk_, ub_) do { \
        const int cp0_ = (chunk_) << 4; \
        _Pragma("unroll 1") \
        for (int id = tid; id < xf4; id += 256) { \
            int cp   = id / (R * 10); \
            int rem  = id - cp * (R * 10); \
            int rowi = rem / 10; \
            int c4   = rem - rowi * 10; \
            int h    = h0 + rowi; \
            int iw0  = c4 * 4 - 4; \
            bool valid = ((unsigned)h < HW) && ((unsigned)iw0 < HW); \
            const __half2* src = g_xh + (((size_t)b * 128 + cp0_ + cp) << 10) \
                + (valid ? h * 32 + iw0 : 0); \
            cpa16((ub_) + (u32)(cp * CST2 + rowi * 40 + c4 * 4) * 4, src, valid); \
        } \
    } while (0)

    const int T = 8 * kk;

    ISSUE_X(0, uXs[0]);
    ISSUE_A(0, 0, uAs[0]);
    CP_COMMIT();

    int r = 0, s = 0;
    #pragma unroll 1
    for (int i = 0; i < T; i++) {
        const int chunk = i / kk;
        CP_WAIT(0);
        __syncthreads();
        if (i + 1 < T) {
            const int i1 = i + 1;
            const int c1 = i1 / kk, rs1 = i1 - c1 * kk;
            if (rs1 == 0) ISSUE_X(c1, uXs[c1 & 1]);
            ISSUE_A(c1, rs1, uAs[i1 & 1]);
            CP_COMMIT();
        }

        // ---- compute step i: 2 k16-steps over this 32-channel chunk ----
        const u32* Aw = (const u32*)(smem + (i & 1) * AS_BYTES);
        const u32* Bw = (const u32*)(smem + 2 * AS_BYTES + (chunk & 1) * XS_BYTES);
        const int arow = wm * 64 + g;
        const int shift = r * 40 + (s - pk + 4);
        #pragma unroll
        for (int ks = 0; ks < 2; ks++) {
            u32 ra[4][4];
            #pragma unroll
            for (int mt = 0; mt < 4; mt++) {
                const u32* ap = Aw + (arow + mt * 16) * 20 + ks * 8 + t;
                ra[mt][0] = ap[0];
                ra[mt][1] = ap[8 * 20];
                ra[mt][2] = ap[4];
                ra[mt][3] = ap[8 * 20 + 4];
            }
            u32 rb[8][2];
            const u32* bp0 = Bw + (t + ks * 8) * CST2 + shift;
            const u32* bp1 = bp0 + 4 * CST2;
            #pragma unroll
            for (int nt = 0; nt < 8; nt++) {
                rb[nt][0] = bp0[pixbase[nt]];
                rb[nt][1] = bp1[pixbase[nt]];
            }
            #pragma unroll
            for (int mt = 0; mt < 4; mt++)
                #pragma unroll
                for (int nt = 0; nt < 8; nt++)
                    mma_f16(acc[mt][nt], ra[mt][0], ra[mt][1], ra[mt][2], ra[mt][3],
                            rb[nt][0], rb[nt][1]);
        }
        if (++s == k) { s = 0; if (++r == k) r = 0; }
    }

    // ---- epilogue: += class embedding, store ----
    const int yb = g_y[b];
    const int ocg = oct * 128 + wm * 64;
    #pragma unroll
    for (int mt = 0; mt < 4; mt++) {
        int oc_lo = ocg + mt * 16 + g;
        int oc_hi = oc_lo + 8;
        float ev_lo = eptr[yb * OUT_C + oc_lo];
        float ev_hi = eptr[yb * OUT_C + oc_hi];
        float* base_lo = out + (size_t)(b * OUT_C + oc_lo) * NPIX + pband * 256;
        float* base_hi = out + (size_t)(b * OUT_C + oc_hi) * NPIX + pband * 256;
        #pragma unroll
        for (int nt = 0; nt < 8; nt++) {
            int p = wn * 64 + nt * 8 + 2 * t;
            float2 vlo = make_float2(acc[mt][nt][0] + ev_lo, acc[mt][nt][1] + ev_lo);
            float2 vhi = make_float2(acc[mt][nt][2] + ev_hi, acc[mt][nt][3] + ev_hi);
            *(float2*)(base_lo + p) = vlo;
            *(float2*)(base_hi + p) = vhi;
        }
    }
}

// ---------------- launcher ----------------
extern "C" void kernel_launch(void* const* d_in, const int* in_sizes, int n_in,
                              void* d_out, int out_size) {
    const float* x = nullptr;
    const int *yr = nullptr, *ar = nullptr;
    const float* w[4] = {nullptr, nullptr, nullptr, nullptr};
    const float* e[4] = {nullptr, nullptr, nullptr, nullptr};
    int ne = 0, n64 = 0;

    for (int i = 0; i < n_in; i++) {
        int sz = in_sizes[i];
        const void* p = d_in[i];
        if      (sz == 16777216) x = (const float*)p;
        else if (sz == 64)       { if (n64++ == 0) yr = (const int*)p; else ar = (const int*)p; }
        else if (sz == 65536)    w[0] = (const float*)p;
        else if (sz == 589824)   w[1] = (const float*)p;
        else if (sz == 1638400)  w[2] = (const float*)p;
        else if (sz == 3211264)  w[3] = (const float*)p;
        else if (sz == 256000)   { if (ne < 4) e[ne++] = (const float*)p; }
    }

    cudaFuncSetAttribute(conv_mma, cudaFuncAttributeMaxDynamicSharedMemorySize, SMEM_BYTES);

    decode_idx<<<1, 64>>>(yr, ar);
    transform_w<<<dim3(1024, 4), 256>>>(w[0], w[1], w[2], w[3]);
    transform_x<<<2048, 256>>>(x);
    conv_mma<<<512, 256, SMEM_BYTES>>>(e[0], e[1], e[2], e[3], (float*)d_out);
}

// round 11
// speedup vs baseline: 9.0903x; 1.1931x over previous
#include <cuda_runtime.h>
#include <cuda_fp16.h>
#include <cstdint>

typedef uint32_t u32;

#define IN_C  256
#define OUT_C 256
#define HW    32
#define NB    64
#define NPIX  1024

__device__ int g_y[NB];
__device__ int g_arc[NB];
__device__ int g_order[NB];
// fragment-packed fp16 weights: [br][rs][chunk8][tile16][ks2][lane32][4 words]
__device__ u32 g_wf[2752512];
// repacked fp16 x: [b][pix][chunk8][ks2][slot8] words; slot order cp(0,4,1,5,2,6,3,7)
__device__ u32 g_xb[8388608];

__constant__ int c_woffw[4] = {0, 32768, 327680, 1146880};

// ---------------- helpers ----------------
__device__ __forceinline__ u32 smem_u32(const void* p) {
    u32 a; asm("{ .reg .u64 t; cvta.to.shared.u64 t, %1; cvt.u32.u64 %0, t; }" : "=r"(a) : "l"(p));
    return a;
}
__device__ __forceinline__ void cpa16(u32 dst, const void* src, bool valid) {
    int sz = valid ? 16 : 0;
    asm volatile("cp.async.ca.shared.global [%0], [%1], 16, %2;"
                 :: "r"(dst), "l"(src), "r"(sz) : "memory");
}
#define CP_COMMIT() asm volatile("cp.async.commit_group;" ::: "memory")
#define CP_WAIT(n)  asm volatile("cp.async.wait_group %0;" :: "n"(n) : "memory")

__device__ __forceinline__ void mma_f16(float* c, u32 a0, u32 a1, u32 a2, u32 a3,
                                        u32 b0, u32 b1) {
    asm volatile("mma.sync.aligned.m16n8k16.row.col.f32.f16.f16.f32 "
                 "{%0,%1,%2,%3}, {%4,%5,%6,%7}, {%8,%9}, {%0,%1,%2,%3};"
                 : "+f"(c[0]), "+f"(c[1]), "+f"(c[2]), "+f"(c[3])
                 : "r"(a0), "r"(a1), "r"(a2), "r"(a3), "r"(b0), "r"(b1));
}
__device__ __forceinline__ void lds64(u32& r0, u32& r1, u32 addr) {
    asm volatile("ld.shared.v2.b32 {%0, %1}, [%2];" : "=r"(r0), "=r"(r1) : "r"(addr));
}
__device__ __forceinline__ u32 packh2(float a, float b) {
    __half2 h = __floats2half2_rn(a, b);
    return *(u32*)&h;
}

// ---------------- prep kernels ----------------
__global__ void decode_idx(const int* __restrict__ yr, const int* __restrict__ ar) {
    __shared__ int is64;
    int t = threadIdx.x;
    if (t == 0) {
        int acc = 0;
        for (int i = 1; i < NB; i += 2) acc |= yr[i];
        is64 = (acc == 0) ? 1 : 0;
    }
    __syncthreads();
    if (t < NB) {
        int st = is64 ? 2 : 1;
        g_y[t]   = yr[t * st];
        g_arc[t] = ar[t * st];
    }
    __syncthreads();
    if (t == 0) {
        int n = 0;
        for (int br = 3; br >= 0; br--)
            for (int i = 0; i < NB; i++)
                if (g_arc[i] == br) g_order[n++] = i;
    }
}

// Pack weights into fragment-lane order.
__global__ void transform_w(const float* __restrict__ w0, const float* __restrict__ w1,
                            const float* __restrict__ w2, const float* __restrict__ w3) {
    int br = blockIdx.y;
    const float* w = (br == 0) ? w0 : (br == 1) ? w1 : (br == 2) ? w2 : w3;
    int k = 2 * br + 1, kk = k * k;
    int off = c_woffw[br];
    int total = kk * 32768;
    for (int i = blockIdx.x * 256 + threadIdx.x; i < total; i += gridDim.x * 256) {
        int rs   = i >> 15;
        int rem  = i & 32767;
        int chunk = rem >> 12;
        int rem3 = rem & 4095;
        int tile = rem3 >> 8;
        int rem4 = rem3 & 255;
        int ks   = rem4 >> 7;
        int rem5 = rem4 & 127;
        int lane = rem5 >> 2, q = rem5 & 3;
        int g = lane >> 2, t = lane & 3;
        int row = tile * 16 + g + ((q & 1) << 3);
        int cl  = t + ((q >> 1) << 2);
        int ch  = chunk * 32 + ks * 16 + cl * 2;
        int base = (row * 256 + ch) * kk + rs;
        g_wf[off + i] = packh2(w[base], w[base + kk]);
    }
}

// Repack x channel-innermost with cp interleave, via smem transpose.
__global__ void transform_x(const float* __restrict__ x) {
    __shared__ __half sm[32][132];
    int b  = blockIdx.x >> 3;
    int pb = blockIdx.x & 7;
    int tid = threadIdx.x;
    for (int chunk = 0; chunk < 8; chunk++) {
        __syncthreads();
        for (int j = tid; j < 32 * 128; j += 256) {
            int c = j >> 7, p = j & 127;
            sm[c][p] = __float2half_rn(
                x[(((size_t)b * 256 + chunk * 32 + c) << 10) + pb * 128 + p]);
        }
        __syncthreads();
        for (int j = tid; j < 128 * 16; j += 256) {
            int p = j >> 4, wd = j & 15;
            int ks = wd >> 3, s = wd & 7;
            int cl = (s >> 1) + ((s & 1) << 2);
            int ch = ks * 16 + cl * 2;
            u32 val = packh2(__half2float(sm[ch][p]), __half2float(sm[ch + 1][p]));
            g_xb[((size_t)b << 17) + (size_t)(pb * 128 + p) * 128 + chunk * 16 + wd] = val;
        }
    }
}

// ---------------- main kernel ----------------
// CTA: (b, oct, pband). 256 thr = 8 warps (2m x 4n), warp tile 64oc x 64pix.
// A: fragment-packed LDG.128 direct to registers (no smem, no per-rs barrier).
// B smem: [ks2][R][40 cols][8 words], pixel stride 8 words (conflict-free LDS.64).
#define SMEM_BYTES (2 * 640 * 14 * 4)   // 2 buffers x 640*R_max words

__global__ void __launch_bounds__(256, 1)
conv_mma(const float* __restrict__ e0_, const float* __restrict__ e1_,
         const float* __restrict__ e2_, const float* __restrict__ e3_,
         float* __restrict__ out)
{
    extern __shared__ u32 smem[];
    const u32 sb = smem_u32(smem);

    const int tid  = threadIdx.x;
    const int wid  = tid >> 5, lane = tid & 31;
    const int g    = lane >> 2, t = lane & 3;
    const int wm   = wid >> 2;
    const int wn   = wid & 3;

    const int b     = g_order[blockIdx.x >> 3];
    const int oct   = (blockIdx.x >> 2) & 1;
    const int pband = blockIdx.x & 3;

    const int br = g_arc[b];
    const int k  = 2 * br + 1, pk = br, kk = k * k;
    const int R  = 7 + k;
    const int XW = 640 * R;                        // words per X buffer
    const float* eptr = (br == 0) ? e0_ : (br == 1) ? e1_ : (br == 2) ? e2_ : e3_;
    const int woffw = c_woffw[br];

    const u32 uX[2] = { sb, sb + (u32)XW * 4 };

    // per-nt pixel word offset within a (ks, shift) view, incl. fragment 2t
    int pixw[8];
    #pragma unroll
    for (int nt = 0; nt < 8; nt++) {
        int p = wn * 64 + nt * 8 + g;
        pixw[nt] = ((p >> 5) * 40 + (p & 31)) * 8 + 2 * t;
    }

    float acc[4][8][4];
    #pragma unroll
    for (int mt = 0; mt < 4; mt++)
        #pragma unroll
        for (int nt = 0; nt < 8; nt++)
            #pragma unroll
            for (int q = 0; q < 4; q++)
                acc[mt][nt][q] = 0.0f;

    const int h0   = pband * 8 - pk;
    const int NCP  = 160 * R;
    const int T80R = 80 * R;
    const u32* xb_img = g_xb + ((size_t)b << 17);

    #define ISSUE_X(chunk_, ub_) do { \
        _Pragma("unroll 1") \
        for (int id = tid; id < NCP; id += 256) { \
            int ks  = (id >= T80R); \
            int rem = id - ks * T80R; \
            int row = rem / 80; \
            int q_  = rem - row * 80; \
            int col = q_ >> 1, hh = q_ & 1; \
            int hr  = h0 + row, ic = col - 4; \
            bool valid = ((unsigned)hr < HW) && ((unsigned)ic < HW); \
            int pix = valid ? (hr * 32 + ic) : 0; \
            const u32* src = xb_img + (size_t)pix * 128 + (chunk_) * 16 + ks * 8 + hh * 4; \
            u32 dst = (ub_) + (u32)(ks * R * 320 + (row * 40 + col) * 8 + hh * 4) * 4; \
            cpa16(dst, src, valid); \
        } \
    } while (0)

    ISSUE_X(0, uX[0]);
    CP_COMMIT();

    #pragma unroll 1
    for (int chunk = 0; chunk < 8; chunk++) {
        CP_WAIT(0);
        __syncthreads();
        if (chunk < 7) {
            ISSUE_X(chunk + 1, uX[(chunk + 1) & 1]);
            CP_COMMIT();
        }
        const u32 xbuf = uX[chunk & 1];
        // warp's A fragment base for this chunk: [rs][chunk][tile][ks][lane][4]
        const uint4* wstep = (const uint4*)(g_wf + woffw
            + (size_t)((chunk * 16 + oct * 8 + wm * 4) * 256) + (lane << 2));

        int r = 0, s = 0;
        #pragma unroll 1
        for (int rs = 0; rs < kk; rs++) {
            // ---- A: 8 coalesced LDG.128 (L2-resident), MLP=8 ----
            // layout: tile stride = 64 uint4, ks stride = 32 uint4
            uint4 a[8];
            const uint4* ap = wstep + (size_t)rs * 8192;   // 32768 words = 8192 uint4
            #pragma unroll
            for (int j = 0; j < 8; j++)
                a[j] = ap[j * 32];                          // j = mt*2+ks

            const int shiftw = (r * 40 + s - pk + 4) * 8;
            #pragma unroll
            for (int ks = 0; ks < 2; ks++) {
                u32 rb[8][2];
                const u32 bka = xbuf + (u32)(ks * R * 320 + shiftw) * 4;
                #pragma unroll
                for (int nt = 0; nt < 8; nt++)
                    lds64(rb[nt][0], rb[nt][1], bka + (u32)pixw[nt] * 4);
                #pragma unroll
                for (int mt = 0; mt < 4; mt++) {
                    const uint4 av = a[mt * 2 + ks];
                    #pragma unroll
                    for (int nt = 0; nt < 8; nt++)
                        mma_f16(acc[mt][nt], av.x, av.y, av.z, av.w,
                                rb[nt][0], rb[nt][1]);
                }
            }
            if (++s == k) { s = 0; ++r; }
        }
    }

    // ---- epilogue: += class embedding, store ----
    const int yb = g_y[b];
    const int ocg = oct * 128 + wm * 64;
    #pragma unroll
    for (int mt = 0; mt < 4; mt++) {
        int oc_lo = ocg + mt * 16 + g;
        int oc_hi = oc_lo + 8;
        float ev_lo = eptr[yb * OUT_C + oc_lo];
        float ev_hi = eptr[yb * OUT_C + oc_hi];
        float* base_lo = out + (size_t)(b * OUT_C + oc_lo) * NPIX + pband * 256;
        float* base_hi = out + (size_t)(b * OUT_C + oc_hi) * NPIX + pband * 256;
        #pragma unroll
        for (int nt = 0; nt < 8; nt++) {
            int p = wn * 64 + nt * 8 + 2 * t;
            float2 vlo = make_float2(acc[mt][nt][0] + ev_lo, acc[mt][nt][1] + ev_lo);
            float2 vhi = make_float2(acc[mt][nt][2] + ev_hi, acc[mt][nt][3] + ev_hi);
            *(float2*)(base_lo + p) = vlo;
            *(float2*)(base_hi + p) = vhi;
        }
    }
}

// ---------------- launcher ----------------
extern "C" void kernel_launch(void* const* d_in, const int* in_sizes, int n_in,
                              void* d_out, int out_size) {
    const float* x = nullptr;
    const int *yr = nullptr, *ar = nullptr;
    const float* w[4] = {nullptr, nullptr, nullptr, nullptr};
    const float* e[4] = {nullptr, nullptr, nullptr, nullptr};
    int ne = 0, n64 = 0;

    for (int i = 0; i < n_in; i++) {
        int sz = in_sizes[i];
        const void* p = d_in[i];
        if      (sz == 16777216) x = (const float*)p;
        else if (sz == 64)       { if (n64++ == 0) yr = (const int*)p; else ar = (const int*)p; }
        else if (sz == 65536)    w[0] = (const float*)p;
        else if (sz == 589824)   w[1] = (const float*)p;
        else if (sz == 1638400)  w[2] = (const float*)p;
        else if (sz == 3211264)  w[3] = (const float*)p;
        else if (sz == 256000)   { if (ne < 4) e[ne++] = (const float*)p; }
    }

    cudaFuncSetAttribute(conv_mma, cudaFuncAttributeMaxDynamicSharedMemorySize, SMEM_BYTES);

    decode_idx<<<1, 64>>>(yr, ar);
    transform_w<<<dim3(512, 4), 256>>>(w[0], w[1], w[2], w[3]);
    transform_x<<<512, 256>>>(x);
    conv_mma<<<512, 256, SMEM_BYTES>>>(e[0], e[1], e[2], e[3], (float*)d_out);
}